// round 16
// baseline (speedup 1.0000x reference)
#include <cuda_runtime.h>
#include <cuda_fp16.h>
#include <cstdint>

// ---------------------------------------------------------------------------
// v14 = R4 (447us) + mma POLE BALANCING between the two warp groups.
//   L0 warps: 24 -> 20 mma4/step (4 hh + 6 ih + unpack-add of partial ring)
//   L1 warps: 16 -> 20 mma4/step (16 main + 4 partial ih0[kt6,7]@x, computed
//             ONE step ahead into a packed-f16 ring: P[k] = Wih0[67]@x(k+1))
// Legality: x is feed-forward; with a 4-slot x ring, x(k+2) is barrier-
// published when L1 computes P[k+1] during interval k; L0 consumes P[k]
// (published at the end of interval k-1). Everything else == R4: one global
// bar.sync per step, f32 tanh.approx cell, h double-buffers, register frags.
// ---------------------------------------------------------------------------

namespace {

constexpr int T_ = 512, I_ = 128, H_ = 64, E_ = 128, C_ = 100;
constexpr int BT = 8, NCTA = 128, NTHR = 512;

constexpr int SWI = 136;
constexpr int SWH = 72;
constexpr int SXS = 136;
constexpr int SHS = 72;
constexpr int XROW = BT * SXS;      // halves per x slot (1088)
constexpr int HROW = BT * SHS;      // halves per h slot (576)

constexpr int OFF_WIH0 = 0;         // 69632
constexpr int OFF_WHH0 = 69632;     // 36864
constexpr int OFF_WIH1 = 106496;    // 36864
constexpr int OFF_WHH1 = 143360;    // 36864
constexpr int OFF_B0   = 180224;    // 1024
constexpr int OFF_B1   = 181248;    // 1024
constexpr int OFF_X    = 182272;    // 4 slots * 2176 = 8704
constexpr int OFF_H0   = 190976;    // 2 * 1152
constexpr int OFF_H1   = 193280;    // 2 * 1152
constexpr int OFF_P    = 195584;    // 2 slots * 4096 = 8192 (partial ring)
constexpr int OFF_HF   = 203776;    // 2048
constexpr int OFF_E    = 205824;    // 4096
constexpr int OFF_F    = 209920;    // 4096
constexpr int SMEM_TOTAL = 214016;

#define BARRIER() asm volatile("bar.sync 0;" ::: "memory")

__device__ __forceinline__ float tanh_ap(float x) {
    float y;
    asm("tanh.approx.f32 %0, %1;" : "=f"(y) : "f"(x));
    return y;
}
__device__ __forceinline__ float fsig(float x) {
    return fmaf(0.5f, tanh_ap(0.5f * x), 0.5f);
}

__device__ __forceinline__ void mma4(float c[4], const uint32_t a[4],
                                     uint32_t b0, uint32_t b1) {
    asm volatile(
        "mma.sync.aligned.m16n8k16.row.col.f32.f16.f16.f32 "
        "{%0,%1,%2,%3},{%4,%5,%6,%7},{%8,%9},{%0,%1,%2,%3};\n"
        : "+f"(c[0]), "+f"(c[1]), "+f"(c[2]), "+f"(c[3])
        : "r"(a[0]), "r"(a[1]), "r"(a[2]), "r"(a[3]), "r"(b0), "r"(b1));
}

template <int KT, int S>
__device__ __forceinline__ void load_w(const half* __restrict__ sW, int wc, int g,
                                       int t, uint32_t f[KT][2][4]) {
#pragma unroll
    for (int kt = 0; kt < KT; kt++)
#pragma unroll
        for (int u = 0; u < 2; u++) {
            const half* p = sW + (wc * 32 + u * 16 + g) * S + kt * 16 + 2 * t;
            f[kt][u][0] = *(const uint32_t*)(p);
            f[kt][u][1] = *(const uint32_t*)(p + 8 * S);
            f[kt][u][2] = *(const uint32_t*)(p + 8);
            f[kt][u][3] = *(const uint32_t*)(p + 8 * S + 8);
        }
}

__device__ __forceinline__ void acc_init(float a[2][4], const float b[2][2]) {
#pragma unroll
    for (int u = 0; u < 2; u++) {
        a[u][0] = b[u][0]; a[u][1] = b[u][0];
        a[u][2] = b[u][1]; a[u][3] = b[u][1];
    }
}

// pack fp32 acc[2][4] -> uint4 of f16 pairs (partial ring entry)
__device__ __forceinline__ uint4 pack_acc(const float a[2][4]) {
    half2 h0 = __floats2half2_rn(a[0][0], a[0][1]);
    half2 h1 = __floats2half2_rn(a[0][2], a[0][3]);
    half2 h2 = __floats2half2_rn(a[1][0], a[1][1]);
    half2 h3 = __floats2half2_rn(a[1][2], a[1][3]);
    uint4 v;
    v.x = *(uint32_t*)&h0; v.y = *(uint32_t*)&h1;
    v.z = *(uint32_t*)&h2; v.w = *(uint32_t*)&h3;
    return v;
}
__device__ __forceinline__ void unpack_add(uint4 v, float a[2][4]) {
    float2 p;
    p = __half22float2(*(half2*)&v.x); a[0][0] += p.x; a[0][1] += p.y;
    p = __half22float2(*(half2*)&v.y); a[0][2] += p.x; a[0][3] += p.y;
    p = __half22float2(*(half2*)&v.z); a[1][0] += p.x; a[1][1] += p.y;
    p = __half22float2(*(half2*)&v.w); a[1][2] += p.x; a[1][3] += p.y;
}

__global__ void __launch_bounds__(NTHR, 1)
lstm_fused(const float* __restrict__ x,
           const float* __restrict__ Wih0, const float* __restrict__ Whh0,
           const float* __restrict__ bih0, const float* __restrict__ bhh0,
           const float* __restrict__ Wih1, const float* __restrict__ Whh1,
           const float* __restrict__ bih1, const float* __restrict__ bhh1,
           const float* __restrict__ Wproj, const float* __restrict__ bproj,
           const float* __restrict__ Wfc1, const float* __restrict__ bfc1,
           const float* __restrict__ Wfc2, const float* __restrict__ bfc2,
           float* __restrict__ out)
{
    extern __shared__ unsigned char smem[];
    half*  sWih0 = (half*)(smem + OFF_WIH0);
    half*  sWhh0 = (half*)(smem + OFF_WHH0);
    half*  sWih1 = (half*)(smem + OFF_WIH1);
    half*  sWhh1 = (half*)(smem + OFF_WHH1);
    float* sB0   = (float*)(smem + OFF_B0);
    float* sB1   = (float*)(smem + OFF_B1);
    half*  sX    = (half*)(smem + OFF_X);
    half*  sH0   = (half*)(smem + OFF_H0);
    half*  sH1   = (half*)(smem + OFF_H1);
    uint4* sP    = (uint4*)(smem + OFF_P);      // 2 slots * 256 entries
    float* sHF   = (float*)(smem + OFF_HF);
    float* sE    = (float*)(smem + OFF_E);
    float* sF    = (float*)(smem + OFF_F);

    const int tid  = threadIdx.x;
    const int lane = tid & 31;
    const int w    = tid >> 5;
    const int wc   = w & 7;
    const int g    = lane >> 2;
    const int t    = lane & 3;
    const int b0r  = blockIdx.x * BT;

    // ---- stage permuted fp16 weights + fused biases + x(0..3) + zero h1 ----
    for (int i = tid; i < 256 * 128; i += NTHR) {
        int p = i >> 7, k = i & 127;
        int m = (((p >> 4) & 1) * 2 + ((p >> 3) & 1)) * 64 + (p >> 5) * 8 + (p & 7);
        sWih0[p * SWI + k] = __float2half(Wih0[m * 128 + k]);
    }
    for (int i = tid; i < 256 * 64; i += NTHR) {
        int p = i >> 6, k = i & 63;
        int m = (((p >> 4) & 1) * 2 + ((p >> 3) & 1)) * 64 + (p >> 5) * 8 + (p & 7);
        sWhh0[p * SWH + k] = __float2half(Whh0[m * 64 + k]);
        sWih1[p * SWH + k] = __float2half(Wih1[m * 64 + k]);
        sWhh1[p * SWH + k] = __float2half(Whh1[m * 64 + k]);
    }
    for (int i = tid; i < 256; i += NTHR) {
        sB0[i] = bih0[i] + bhh0[i];
        sB1[i] = bih1[i] + bhh1[i];
    }
    for (int i = tid; i < 2 * HROW; i += NTHR)
        sH1[i] = __float2half(0.f);                      // h1(-1) = 0
    for (int i = tid; i < 4 * BT * 128; i += NTHR) {     // x(0..3) -> slots 0..3
        int s = i >> 10, rem = i & 1023;
        int r = rem >> 7, c = rem & 127;
        sX[s * XROW + r * SXS + c] =
            __float2half(x[((size_t)(b0r + r) * T_ + s) * I_ + c]);
    }
    __syncthreads();

    const int n0 = 2 * t;
    const int j  = wc * 8 + g;

    if (w < 8) {
        // ================= layer-0 warps =================
        uint32_t fih0[8][2][4], fhh0[4][2][4];
        load_w<8, SWI>(sWih0, wc, g, t, fih0);   // kt6,7 used only in prologue
        load_w<4, SWH>(sWhh0, wc, g, t, fhh0);
        float bb0[2][2];
#pragma unroll
        for (int u = 0; u < 2; u++)
#pragma unroll
            for (int v = 0; v < 2; v++)
                bb0[u][v] = sB0[(2 * u + v) * 64 + wc * 8 + g];

        float c00 = 0.f, c01 = 0.f;

        {   // prologue: t=0 cell (full 8-kt ih, no recurrent term)
            float a[2][4];
            acc_init(a, bb0);
#pragma unroll
            for (int kt = 0; kt < 8; kt++) {
                const half* p = sX + g * SXS + kt * 16 + 2 * t;   // x(0): slot 0
                uint32_t b0 = *(const uint32_t*)(p);
                uint32_t b1 = *(const uint32_t*)(p + 8);
                mma4(a[0], fih0[kt][0], b0, b1);
                mma4(a[1], fih0[kt][1], b0, b1);
            }
            float i0 = fsig(a[0][0]), i1 = fsig(a[0][1]);
            float g0 = tanh_ap(a[1][0]), g1 = tanh_ap(a[1][1]);
            float o0 = fsig(a[1][2]), o1 = fsig(a[1][3]);
            c00 = i0 * g0; c01 = i1 * g1;
            sH0[n0 * SHS + j]       = __float2half(o0 * tanh_ap(c00));
            sH0[(n0 + 1) * SHS + j] = __float2half(o1 * tanh_ap(c01));
        }
        BARRIER();                                       // S1

        for (int k = 0; k < T_; k++) {
            const int p = k & 1;
            float a[2][4];
            acc_init(a, bb0);
            const half* H0 = sH0 + p * HROW;
#pragma unroll
            for (int kt = 0; kt < 4; kt++) {             // hh @ h0(k)
                const half* q = H0 + g * SHS + kt * 16 + 2 * t;
                uint32_t b0 = *(const uint32_t*)(q);
                uint32_t b1 = *(const uint32_t*)(q + 8);
                mma4(a[0], fhh0[kt][0], b0, b1);
                mma4(a[1], fhh0[kt][1], b0, b1);
            }
            const half* X = sX + ((k + 1) & 3) * XROW;   // x(k+1)
#pragma unroll
            for (int kt = 0; kt < 6; kt++) {             // ih kt 0..5
                const half* q = X + g * SXS + kt * 16 + 2 * t;
                uint32_t b0 = *(const uint32_t*)(q);
                uint32_t b1 = *(const uint32_t*)(q + 8);
                mma4(a[0], fih0[kt][0], b0, b1);
                mma4(a[1], fih0[kt][1], b0, b1);
            }
            // partial P[k] = Wih0[kt6,7] @ x(k+1), made by L1 in interval k-1
            unpack_add(sP[(k & 1) * 256 + wc * 32 + lane], a);
            // L0 cell for t = k+1 (phantom at k = T_-1, harmless)
            float i0 = fsig(a[0][0]), i1 = fsig(a[0][1]);
            float f0 = fsig(a[0][2]), f1 = fsig(a[0][3]);
            float g0 = tanh_ap(a[1][0]), g1 = tanh_ap(a[1][1]);
            float o0 = fsig(a[1][2]), o1 = fsig(a[1][3]);
            c00 = f0 * c00 + i0 * g0;
            c01 = f1 * c01 + i1 * g1;
            half* h0w = sH0 + (1 - p) * HROW;
            h0w[n0 * SHS + j]       = __float2half(o0 * tanh_ap(c00));
            h0w[(n0 + 1) * SHS + j] = __float2half(o1 * tanh_ap(c01));
            BARRIER();
        }
    } else {
        // ================= layer-1 warps =================
        uint32_t fih1[4][2][4], fhh1[4][2][4], fp0[2][2][4];
        load_w<4, SWH>(sWih1, wc, g, t, fih1);
        load_w<4, SWH>(sWhh1, wc, g, t, fhh1);
        load_w<2, SWI>(sWih0 + 96, wc, g, t, fp0);       // Wih0 kt 6,7
        float bb1[2][2];
#pragma unroll
        for (int u = 0; u < 2; u++)
#pragma unroll
            for (int v = 0; v < 2; v++)
                bb1[u][v] = sB1[(2 * u + v) * 64 + wc * 8 + g];

        float c10 = 0.f, c11 = 0.f;

        // x LDG pipeline: warp = batch row, lane = 4 floats, 2-deep
        const int xr = wc, xi = lane * 4;
        const float* xrow = x + ((size_t)(b0r + xr) * T_) * I_ + xi;
        float4 xpA = *(const float4*)(xrow + 4 * (size_t)I_);   // x(4)
        float4 xpB = *(const float4*)(xrow + 5 * (size_t)I_);   // x(5)

        {   // prologue: P[0] = Wih0[67] @ x(1) -> P slot 0
            float pa[2][4];
#pragma unroll
            for (int u = 0; u < 2; u++)
#pragma unroll
                for (int e = 0; e < 4; e++) pa[u][e] = 0.f;
            const half* X1 = sX + 1 * XROW;
#pragma unroll
            for (int kt = 0; kt < 2; kt++) {
                const half* q = X1 + g * SXS + (6 + kt) * 16 + 2 * t;
                uint32_t b0 = *(const uint32_t*)(q);
                uint32_t b1 = *(const uint32_t*)(q + 8);
                mma4(pa[0], fp0[kt][0], b0, b1);
                mma4(pa[1], fp0[kt][1], b0, b1);
            }
            sP[0 * 256 + wc * 32 + lane] = pack_acc(pa);
        }
        BARRIER();                                       // S1

        for (int k = 0; k < T_; k++) {
            const int p = k & 1;
            {   // x pipeline: STS x(k+4) -> slot k&3, fetch x(k+6)
                half* xw = sX + (k & 3) * XROW;
                *(half2*)(xw + xr * SXS + xi)     = __floats2half2_rn(xpA.x, xpA.y);
                *(half2*)(xw + xr * SXS + xi + 2) = __floats2half2_rn(xpA.z, xpA.w);
                xpA = xpB;
                int tn = k + 6; if (tn > T_ - 1) tn = T_ - 1;
                xpB = *(const float4*)(xrow + (size_t)tn * I_);
            }
            float a[2][4];
            acc_init(a, bb1);
            const half* H0 = sH0 + p * HROW;
            const half* H1 = sH1 + p * HROW;
#pragma unroll
            for (int kt = 0; kt < 4; kt++) {
                const half* q0 = H0 + g * SHS + kt * 16 + 2 * t;
                uint32_t b0 = *(const uint32_t*)(q0);
                uint32_t b1 = *(const uint32_t*)(q0 + 8);
                mma4(a[0], fih1[kt][0], b0, b1);
                mma4(a[1], fih1[kt][1], b0, b1);
                const half* q1 = H1 + g * SHS + kt * 16 + 2 * t;
                uint32_t d0 = *(const uint32_t*)(q1);
                uint32_t d1 = *(const uint32_t*)(q1 + 8);
                mma4(a[0], fhh1[kt][0], d0, d1);
                mma4(a[1], fhh1[kt][1], d0, d1);
            }
            {   // partial for next step: P[k+1] = Wih0[67] @ x(k+2)
                float pa[2][4];
#pragma unroll
                for (int u = 0; u < 2; u++)
#pragma unroll
                    for (int e = 0; e < 4; e++) pa[u][e] = 0.f;
                const half* X2 = sX + ((k + 2) & 3) * XROW;
#pragma unroll
                for (int kt = 0; kt < 2; kt++) {
                    const half* q = X2 + g * SXS + (6 + kt) * 16 + 2 * t;
                    uint32_t b0 = *(const uint32_t*)(q);
                    uint32_t b1 = *(const uint32_t*)(q + 8);
                    mma4(pa[0], fp0[kt][0], b0, b1);
                    mma4(pa[1], fp0[kt][1], b0, b1);
                }
                sP[((k + 1) & 1) * 256 + wc * 32 + lane] = pack_acc(pa);
            }
            // L1 cell for t = k
            float i0 = fsig(a[0][0]), i1 = fsig(a[0][1]);
            float f0 = fsig(a[0][2]), f1 = fsig(a[0][3]);
            float g0 = tanh_ap(a[1][0]), g1 = tanh_ap(a[1][1]);
            float o0 = fsig(a[1][2]), o1 = fsig(a[1][3]);
            c10 = f0 * c10 + i0 * g0;
            c11 = f1 * c11 + i1 * g1;
            float h0v = o0 * tanh_ap(c10), h1v = o1 * tanh_ap(c11);
            half* h1w = sH1 + (1 - p) * HROW;
            h1w[n0 * SHS + j]       = __float2half(h0v);
            h1w[(n0 + 1) * SHS + j] = __float2half(h1v);
            if (k == T_ - 1) {
                sHF[n0 * H_ + j]       = h0v;
                sHF[(n0 + 1) * H_ + j] = h1v;
            }
            BARRIER();
        }
    }

    __syncthreads();

    // ---- head: proj -> relu -> fc1 -> relu -> fc2 ----
#pragma unroll
    for (int q = 0; q < 2; q++) {
        int idx = tid + q * NTHR;
        int r = idx >> 7, e = idx & 127;
        float a = bproj[e];
        const float* wp = Wproj + e * H_;
        const float* hp = sHF + r * H_;
#pragma unroll 8
        for (int kk = 0; kk < H_; kk++) a += hp[kk] * wp[kk];
        sE[r * E_ + e] = fmaxf(a, 0.f);
    }
    __syncthreads();
#pragma unroll
    for (int q = 0; q < 2; q++) {
        int idx = tid + q * NTHR;
        int r = idx >> 7, e = idx & 127;
        float a = bfc1[e];
        const float* wp = Wfc1 + e * E_;
        const float* hp = sE + r * E_;
#pragma unroll 8
        for (int kk = 0; kk < E_; kk++) a += hp[kk] * wp[kk];
        sF[r * E_ + e] = fmaxf(a, 0.f);
    }
    __syncthreads();
    for (int idx = tid; idx < BT * C_; idx += NTHR) {
        int r = idx / C_, c = idx - r * C_;
        float a = bfc2[c];
        const float* wp = Wfc2 + c * E_;
        const float* hp = sF + r * E_;
#pragma unroll 8
        for (int kk = 0; kk < E_; kk++) a += hp[kk] * wp[kk];
        out[(size_t)(b0r + r) * C_ + c] = a;
    }
}

}  // namespace

extern "C" void kernel_launch(void* const* d_in, const int* in_sizes, int n_in,
                              void* d_out, int out_size) {
    cudaFuncSetAttribute(lstm_fused, cudaFuncAttributeMaxDynamicSharedMemorySize,
                         SMEM_TOTAL);
    lstm_fused<<<NCTA, NTHR, SMEM_TOTAL>>>(
        (const float*)d_in[0],
        (const float*)d_in[1],  (const float*)d_in[2],
        (const float*)d_in[3],  (const float*)d_in[4],
        (const float*)d_in[5],  (const float*)d_in[6],
        (const float*)d_in[7],  (const float*)d_in[8],
        (const float*)d_in[9],  (const float*)d_in[10],
        (const float*)d_in[11], (const float*)d_in[12],
        (const float*)d_in[13], (const float*)d_in[14],
        (float*)d_out);
}